// round 3
// baseline (speedup 1.0000x reference)
#include <cuda_runtime.h>
#include <cstdint>

// Problem constants
#define BB   16
#define DD   64
#define LL   2048
#define KK   1000
#define KPAD 1024
#define NN   (BB * LL)          // 32768 tokens
#define TM   128                // tokens per block
#define KC   128                // codes per chunk
#define NCHUNK (KPAD / KC)      // 8
#define THREADS 256
#define NBLK (NN / TM)          // 256 blocks
#define XP_STRIDE 66            // u64 units, pair-major x tile
#define EP_STRIDE 66            // u64 units, duplicated code tile

#define OUT_ELEMS (BB * DD * LL)     // 2097152
#define LOSS_OFF  OUT_ELEMS
#define USAGE_OFF (OUT_ELEMS + 1)
#define IDX_OFF   (OUT_ELEMS + 2)

// Per-block loss partials (rewritten every call, no clearing needed).
__device__ float g_partial[NBLK];
// Usage flags: zero at init; vq_main sets, vq_final reads then resets to zero
// -> identical state at the start of every call (graph-replay deterministic).
__device__ int g_flags[KK];

// ---- packed f32x2 helpers ----
__device__ __forceinline__ unsigned long long ffma2(unsigned long long a,
                                                    unsigned long long b,
                                                    unsigned long long c) {
    unsigned long long d;
    asm("fma.rn.f32x2 %0, %1, %2, %3;" : "=l"(d) : "l"(a), "l"(b), "l"(c));
    return d;
}
__device__ __forceinline__ unsigned long long dup2(float v) {
    unsigned long long r;
    asm("mov.b64 %0, {%1, %1};" : "=l"(r) : "f"(v));
    return r;
}
__device__ __forceinline__ unsigned long long pack2(float lo, float hi) {
    unsigned long long r;
    asm("mov.b64 %0, {%1, %2};" : "=l"(r) : "f"(lo), "f"(hi));
    return r;
}
__device__ __forceinline__ void unpack2(unsigned long long v, float& lo, float& hi) {
    asm("mov.b64 {%0, %1}, %2;" : "=f"(lo), "=f"(hi) : "l"(v));
}

// ---- main: distances + argmin + gather + loss partial + usage marks ----
__global__ void __launch_bounds__(THREADS, 2)
vq_main(const float* __restrict__ x, const float* __restrict__ emb,
        float* __restrict__ dout) {
    extern __shared__ char smraw[];
    unsigned long long* xsp = (unsigned long long*)smraw;      // [64 pairs][66]
    unsigned long long* esd = xsp + 64 * XP_STRIDE;            // [128 codes][66] {e,e}
    float* se  = (float*)(esd + KC * EP_STRIDE);               // [128] code norms
    float* xns = se + KC;                                      // [128] token norms
    int*   ii  = (int*)(xns + TM);                             // [128] final idx
    // overlays (used only after the mainloop is done with xsp):
    float* rv = (float*)xsp;                                   // [8][128]
    int*   ri = (int*)(rv + 8 * TM);                           // [8][128]

    const int tid  = threadIdx.x;
    const int warp = tid >> 5;
    const int lane = tid & 31;
    const int b  = blockIdx.x >> 4;
    const int l0 = (blockIdx.x & 15) * TM;
    const int tt = tid & 15;     // token-pair group: pairs {tt, tt+16, tt+32, tt+48}
    const int tc = tid >> 4;     // code group: codes k = tc + 16j, j=0..7

    // Load x tile [d][t] -> pair-major xsp[t/2][d] (coalesced float4 reads)
    #pragma unroll
    for (int it = 0; it < 8; it++) {
        int i = tid + it * THREADS;
        int d = i >> 5, t4 = i & 31;
        float4 v = *(const float4*)(x + ((size_t)(b * DD + d)) * LL + l0 + t4 * 4);
        xsp[(2 * t4) * XP_STRIDE + d]     = pack2(v.x, v.y);
        xsp[(2 * t4 + 1) * XP_STRIDE + d] = pack2(v.z, v.w);
    }
    __syncthreads();

    // Token norms: one thread per pair row, packed accumulate
    if (tid < 64) {
        unsigned long long acc = 0ull;
        const unsigned long long* row = xsp + tid * XP_STRIDE;
        #pragma unroll
        for (int d = 0; d < DD; d += 2) {
            ulonglong2 q = *(const ulonglong2*)(row + d);
            acc = ffma2(q.x, q.x, acc);
            acc = ffma2(q.y, q.y, acc);
        }
        float lo, hi; unpack2(acc, lo, hi);
        xns[2 * tid] = lo; xns[2 * tid + 1] = hi;
    }

    float bestv[8];
    int   besti[8];
    #pragma unroll
    for (int i = 0; i < 8; i++) { bestv[i] = 3.0e38f; besti[i] = 0; }

    for (int c = 0; c < NCHUNK; c++) {
        const int k0 = c * KC;
        __syncthreads();   // previous chunk fully consumed

        // Load code chunk: each thread owns one (code, half-row); writes
        // duplicated {e,e} pairs and computes its half-norm.
        {
            int k = tid >> 1, half = tid & 1;
            int kg = k0 + k;
            float nrm = 0.0f;
            const float4* src = (const float4*)(emb + (size_t)kg * DD + half * 32);
            unsigned long long* dst = esd + k * EP_STRIDE + half * 32;
            #pragma unroll
            for (int q = 0; q < 8; q++) {
                float4 v = (kg < KK) ? src[q] : make_float4(0.f, 0.f, 0.f, 0.f);
                nrm += v.x * v.x + v.y * v.y + v.z * v.z + v.w * v.w;
                ulonglong2 w0, w1;
                w0.x = dup2(v.x); w0.y = dup2(v.y);
                w1.x = dup2(v.z); w1.y = dup2(v.w);
                *(ulonglong2*)(dst + 4 * q)     = w0;
                *(ulonglong2*)(dst + 4 * q + 2) = w1;
            }
            nrm += __shfl_xor_sync(0xffffffffu, nrm, 1);
            if (half == 0) se[k] = (kg < KK) ? nrm : 3.4e38f;
        }
        __syncthreads();

        // 8 token-pairs x 8 codes register tile, two d per iteration.
        unsigned long long acc[8][4];
        #pragma unroll
        for (int j = 0; j < 8; j++)
            #pragma unroll
            for (int p = 0; p < 4; p++) acc[j][p] = 0ull;

        const unsigned long long* ebase = esd + tc * EP_STRIDE;
        #pragma unroll 2
        for (int d = 0; d < DD; d += 2) {
            ulonglong2 xq0 = *(const ulonglong2*)(xsp + (tt     ) * XP_STRIDE + d);
            ulonglong2 xq1 = *(const ulonglong2*)(xsp + (tt + 16) * XP_STRIDE + d);
            ulonglong2 xq2 = *(const ulonglong2*)(xsp + (tt + 32) * XP_STRIDE + d);
            ulonglong2 xq3 = *(const ulonglong2*)(xsp + (tt + 48) * XP_STRIDE + d);
            #pragma unroll
            for (int j = 0; j < 8; j++) {
                ulonglong2 eq = *(const ulonglong2*)(ebase + (16 * j) * EP_STRIDE + d);
                acc[j][0] = ffma2(xq0.x, eq.x, acc[j][0]);
                acc[j][1] = ffma2(xq1.x, eq.x, acc[j][1]);
                acc[j][2] = ffma2(xq2.x, eq.x, acc[j][2]);
                acc[j][3] = ffma2(xq3.x, eq.x, acc[j][3]);
                acc[j][0] = ffma2(xq0.y, eq.y, acc[j][0]);
                acc[j][1] = ffma2(xq1.y, eq.y, acc[j][1]);
                acc[j][2] = ffma2(xq2.y, eq.y, acc[j][2]);
                acc[j][3] = ffma2(xq3.y, eq.y, acc[j][3]);
            }
        }

        // argmin update: m = ||e||^2 - 2*dot   (||x||^2 added at the end)
        #pragma unroll
        for (int j = 0; j < 8; j++) {
            int   kk = k0 + tc + 16 * j;
            float en = se[tc + 16 * j];
            #pragma unroll
            for (int p = 0; p < 4; p++) {
                float d0, d1;
                unpack2(acc[j][p], d0, d1);
                float m0 = fmaf(-2.0f, d0, en);
                float m1 = fmaf(-2.0f, d1, en);
                if (m0 < bestv[2 * p])     { bestv[2 * p]     = m0; besti[2 * p]     = kk; }
                else if (m0 == bestv[2 * p]     && kk < besti[2 * p])     besti[2 * p]     = kk;
                if (m1 < bestv[2 * p + 1]) { bestv[2 * p + 1] = m1; besti[2 * p + 1] = kk; }
                else if (m1 == bestv[2 * p + 1] && kk < besti[2 * p + 1]) besti[2 * p + 1] = kk;
            }
        }
    }
    __syncthreads();   // mainloop done reading xsp -> overlays become legal

    // Warp pre-reduce: the two tc groups in a warp sit at lane and lane^16
    #pragma unroll
    for (int s = 0; s < 8; s++) {
        float ov = __shfl_xor_sync(0xffffffffu, bestv[s], 16);
        int   oi = __shfl_xor_sync(0xffffffffu, besti[s], 16);
        if (ov < bestv[s] || (ov == bestv[s] && oi < besti[s])) {
            bestv[s] = ov; besti[s] = oi;
        }
    }
    if (lane < 16) {
        #pragma unroll
        for (int p = 0; p < 4; p++) {
            int t = 2 * (tt + 16 * p);
            rv[warp * TM + t]     = bestv[2 * p];
            ri[warp * TM + t]     = besti[2 * p];
            rv[warp * TM + t + 1] = bestv[2 * p + 1];
            ri[warp * TM + t + 1] = besti[2 * p + 1];
        }
    }
    __syncthreads();

    if (tid < TM) {
        float bv = rv[tid];
        int   bi = ri[tid];
        #pragma unroll
        for (int g = 1; g < 8; g++) {
            float v  = rv[g * TM + tid];
            int   ix = ri[g * TM + tid];
            if (v < bv || (v == bv && ix < bi)) { bv = v; bi = ix; }
        }
        int n = b * LL + l0 + tid;
        dout[IDX_OFF + n] = (float)bi;
        ii[tid] = bi;
        g_flags[bi] = 1;                 // idempotent usage mark
        se[tid] = xns[tid] + bv;         // min squared distance (loss term)
    }
    __syncthreads();

    // Block loss reduction -> per-block partial
    if (tid < 64) se[tid] += se[tid + 64];
    __syncthreads();
    if (tid < 32) {
        float s = se[tid] + se[tid + 32];
        #pragma unroll
        for (int off = 16; off > 0; off >>= 1)
            s += __shfl_down_sync(0xffffffffu, s, off);
        if (tid == 0) g_partial[blockIdx.x] = s;
    }

    // Gather + transpose write: out[b][d][l] = emb[idx][d] (coalesced stores)
    __syncthreads();
    for (int i = tid; i < DD * TM; i += THREADS) {
        int d = i >> 7, t = i & 127;
        dout[((size_t)(b * DD + d)) * LL + l0 + t] = emb[(size_t)ii[t] * DD + d];
    }
}

// ---- finalize: loss scalar + usage count; resets flags for next call ----
__global__ void __launch_bounds__(1024, 1)
vq_final(float* __restrict__ dout) {
    __shared__ float lsum;
    __shared__ int   cnt;
    int tid = threadIdx.x;
    if (tid == 0) { lsum = 0.0f; cnt = 0; }
    __syncthreads();

    float s = (tid < NBLK) ? g_partial[tid] : 0.0f;
    #pragma unroll
    for (int off = 16; off > 0; off >>= 1)
        s += __shfl_down_sync(0xffffffffu, s, off);
    if ((tid & 31) == 0) atomicAdd(&lsum, s);

    int f = (tid < KK) ? g_flags[tid] : 0;
    #pragma unroll
    for (int off = 16; off > 0; off >>= 1)
        f += __shfl_down_sync(0xffffffffu, f, off);
    if ((tid & 31) == 0) atomicAdd(&cnt, f);
    __syncthreads();

    if (tid < KK) g_flags[tid] = 0;      // restore zero state for next call
    if (tid == 0) {
        dout[LOSS_OFF]  = 11.0f * lsum / (float)(NN * DD);   // (1+10) * MSE
        dout[USAGE_OFF] = (float)cnt;
    }
}

extern "C" void kernel_launch(void* const* d_in, const int* in_sizes, int n_in,
                              void* d_out, int out_size) {
    (void)n_in; (void)out_size;
    const float* x;
    const float* emb;
    if (in_sizes[0] == KK * DD) { emb = (const float*)d_in[0]; x = (const float*)d_in[1]; }
    else                        { x   = (const float*)d_in[0]; emb = (const float*)d_in[1]; }
    float* out = (float*)d_out;

    const int smem_bytes = (64 * XP_STRIDE + KC * EP_STRIDE) * 8   // xsp + esd
                         + (KC + TM) * 4                           // se + xns
                         + TM * 4;                                 // ii
    cudaFuncSetAttribute(vq_main, cudaFuncAttributeMaxDynamicSharedMemorySize,
                         smem_bytes);

    vq_main<<<NBLK, THREADS, smem_bytes>>>(x, emb, out);
    vq_final<<<1, 1024>>>(out);
}

// round 4
// speedup vs baseline: 1.1961x; 1.1961x over previous
#include <cuda_runtime.h>
#include <cstdint>

// Problem constants
#define BB   16
#define DD   64
#define LL   2048
#define KK   1000
#define KPAD 1024
#define NN   (BB * LL)          // 32768 tokens
#define TM   128                // tokens per block
#define KC   128                // codes per chunk
#define NCHUNK (KPAD / KC)      // 8
#define THREADS 256
#define NBLK (NN / TM)          // 256 blocks
#define XP_STRIDE 66            // u64 units, pair-major x tile (132 words = 4 mod 32)
#define ES_STRIDE 68            // floats, code tile (68 = 4 mod 32)

#define OUT_ELEMS (BB * DD * LL)     // 2097152
#define LOSS_OFF  OUT_ELEMS
#define USAGE_OFF (OUT_ELEMS + 1)
#define IDX_OFF   (OUT_ELEMS + 2)

// Per-block loss partials (rewritten every call, no clearing needed).
__device__ float g_partial[NBLK];
// Usage flags: zero at init; vq_main sets, vq_final reads then resets to zero.
__device__ int g_flags[KK];

// ---- packed f32x2 helpers ----
__device__ __forceinline__ unsigned long long ffma2(unsigned long long a,
                                                    unsigned long long b,
                                                    unsigned long long c) {
    unsigned long long d;
    asm("fma.rn.f32x2 %0, %1, %2, %3;" : "=l"(d) : "l"(a), "l"(b), "l"(c));
    return d;
}
__device__ __forceinline__ unsigned long long dup2(float v) {
    unsigned long long r;
    asm("mov.b64 %0, {%1, %1};" : "=l"(r) : "f"(v));
    return r;
}
__device__ __forceinline__ unsigned long long pack2(float lo, float hi) {
    unsigned long long r;
    asm("mov.b64 %0, {%1, %2};" : "=l"(r) : "f"(lo), "f"(hi));
    return r;
}
__device__ __forceinline__ void unpack2(unsigned long long v, float& lo, float& hi) {
    asm("mov.b64 {%0, %1}, %2;" : "=f"(lo), "=f"(hi) : "l"(v));
}

// ---- main: distances + argmin + gather + loss partial + usage marks ----
__global__ void __launch_bounds__(THREADS, 2)
vq_main(const float* __restrict__ x, const float* __restrict__ emb,
        float* __restrict__ dout) {
    extern __shared__ char smraw[];
    unsigned long long* xsp = (unsigned long long*)smraw;      // [64 pairs][66]
    float* es  = (float*)(xsp + 64 * XP_STRIDE);               // [128][68]
    float* se  = es + KC * ES_STRIDE;                          // [128] code norms
    float* xns = se + KC;                                      // [128] token norms
    int*   ii  = (int*)(xns + TM);                             // [128] final idx
    // overlays (legal only after the mainloop stops reading xsp):
    float* rv = (float*)xsp;                                   // [8][128]
    int*   ri = (int*)(rv + 8 * TM);                           // [8][128]

    const int tid  = threadIdx.x;
    const int warp = tid >> 5;
    const int lane = tid & 31;
    const int b  = blockIdx.x >> 4;
    const int l0 = (blockIdx.x & 15) * TM;
    const int tt = tid & 15;     // token-pair group: pairs {tt, tt+16, tt+32, tt+48}
    const int tc = tid >> 4;     // code group: codes k = tc + 16j, j=0..7

    // Load x tile [d][t] -> pair-major xsp[t/2][d] (coalesced float4 reads)
    #pragma unroll
    for (int it = 0; it < 8; it++) {
        int i = tid + it * THREADS;
        int d = i >> 5, t4 = i & 31;
        float4 v = *(const float4*)(x + ((size_t)(b * DD + d)) * LL + l0 + t4 * 4);
        xsp[(2 * t4) * XP_STRIDE + d]     = pack2(v.x, v.y);
        xsp[(2 * t4 + 1) * XP_STRIDE + d] = pack2(v.z, v.w);
    }
    __syncthreads();

    // Token norms: one thread per pair row, packed accumulate
    if (tid < 64) {
        unsigned long long acc = 0ull;
        const unsigned long long* row = xsp + tid * XP_STRIDE;
        #pragma unroll
        for (int d = 0; d < DD; d += 2) {
            ulonglong2 q = *(const ulonglong2*)(row + d);
            acc = ffma2(q.x, q.x, acc);
            acc = ffma2(q.y, q.y, acc);
        }
        float lo, hi; unpack2(acc, lo, hi);
        xns[2 * tid] = lo; xns[2 * tid + 1] = hi;
    }

    float bestv[8];
    int   besti[8];
    #pragma unroll
    for (int i = 0; i < 8; i++) { bestv[i] = 3.0e38f; besti[i] = 0; }

    for (int c = 0; c < NCHUNK; c++) {
        const int k0 = c * KC;
        __syncthreads();   // previous chunk fully consumed

        // Coalesced code-chunk load (R2-proven pattern) with fused norms:
        // i -> (code k, quarter d4); 16 consecutive threads cover one code row.
        #pragma unroll
        for (int it = 0; it < 8; it++) {
            int i = tid + it * THREADS;
            int k = i >> 4, d4 = i & 15;
            int kg = k0 + k;
            float4 v = make_float4(0.f, 0.f, 0.f, 0.f);
            if (kg < KK)
                v = *(const float4*)(emb + (size_t)kg * DD + d4 * 4);
            *(float4*)(es + k * ES_STRIDE + d4 * 4) = v;
            // fused norm: reduce 16 lanes' partials (one code per half-warp)
            float pn = v.x * v.x + v.y * v.y + v.z * v.z + v.w * v.w;
            #pragma unroll
            for (int off = 8; off > 0; off >>= 1)
                pn += __shfl_xor_sync(0xffffffffu, pn, off);
            if (d4 == 0) se[k] = (kg < KK) ? pn : 3.4e38f;
        }
        __syncthreads();

        // 8 token-pairs x 8 codes register tile, two d per iteration.
        // xq: LDS.128 (2 d per pair), banks clean per 8-lane phase.
        // eq: LDS.64 broadcast {e_d,e_d+1}; strided k map keeps banks apart.
        unsigned long long acc[8][4];
        #pragma unroll
        for (int j = 0; j < 8; j++)
            #pragma unroll
            for (int p = 0; p < 4; p++) acc[j][p] = 0ull;

        const float* ebase = es + tc * ES_STRIDE;
        #pragma unroll 2
        for (int d = 0; d < DD; d += 2) {
            ulonglong2 xq0 = *(const ulonglong2*)(xsp + (tt     ) * XP_STRIDE + d);
            ulonglong2 xq1 = *(const ulonglong2*)(xsp + (tt + 16) * XP_STRIDE + d);
            ulonglong2 xq2 = *(const ulonglong2*)(xsp + (tt + 32) * XP_STRIDE + d);
            ulonglong2 xq3 = *(const ulonglong2*)(xsp + (tt + 48) * XP_STRIDE + d);
            #pragma unroll
            for (int j = 0; j < 8; j++) {
                unsigned long long ep =
                    *(const unsigned long long*)(ebase + (16 * j) * ES_STRIDE + d);
                float elo, ehi; unpack2(ep, elo, ehi);
                unsigned long long e0 = dup2(elo);
                unsigned long long e1 = dup2(ehi);
                acc[j][0] = ffma2(xq0.x, e0, acc[j][0]);
                acc[j][1] = ffma2(xq1.x, e0, acc[j][1]);
                acc[j][2] = ffma2(xq2.x, e0, acc[j][2]);
                acc[j][3] = ffma2(xq3.x, e0, acc[j][3]);
                acc[j][0] = ffma2(xq0.y, e1, acc[j][0]);
                acc[j][1] = ffma2(xq1.y, e1, acc[j][1]);
                acc[j][2] = ffma2(xq2.y, e1, acc[j][2]);
                acc[j][3] = ffma2(xq3.y, e1, acc[j][3]);
            }
        }

        // argmin update: m = ||e||^2 - 2*dot   (||x||^2 added at the end)
        #pragma unroll
        for (int j = 0; j < 8; j++) {
            int   kk = k0 + tc + 16 * j;
            float en = se[tc + 16 * j];
            #pragma unroll
            for (int p = 0; p < 4; p++) {
                float d0, d1;
                unpack2(acc[j][p], d0, d1);
                float m0 = fmaf(-2.0f, d0, en);
                float m1 = fmaf(-2.0f, d1, en);
                if (m0 < bestv[2 * p])     { bestv[2 * p]     = m0; besti[2 * p]     = kk; }
                else if (m0 == bestv[2 * p]     && kk < besti[2 * p])     besti[2 * p]     = kk;
                if (m1 < bestv[2 * p + 1]) { bestv[2 * p + 1] = m1; besti[2 * p + 1] = kk; }
                else if (m1 == bestv[2 * p + 1] && kk < besti[2 * p + 1]) besti[2 * p + 1] = kk;
            }
        }
    }
    __syncthreads();   // mainloop done reading xsp -> overlays become legal

    // Warp pre-reduce: the two tc groups in a warp sit at lane and lane^16
    #pragma unroll
    for (int s = 0; s < 8; s++) {
        float ov = __shfl_xor_sync(0xffffffffu, bestv[s], 16);
        int   oi = __shfl_xor_sync(0xffffffffu, besti[s], 16);
        if (ov < bestv[s] || (ov == bestv[s] && oi < besti[s])) {
            bestv[s] = ov; besti[s] = oi;
        }
    }
    if (lane < 16) {
        #pragma unroll
        for (int p = 0; p < 4; p++) {
            int t = 2 * (tt + 16 * p);
            rv[warp * TM + t]     = bestv[2 * p];
            ri[warp * TM + t]     = besti[2 * p];
            rv[warp * TM + t + 1] = bestv[2 * p + 1];
            ri[warp * TM + t + 1] = besti[2 * p + 1];
        }
    }
    __syncthreads();

    if (tid < TM) {
        float bv = rv[tid];
        int   bi = ri[tid];
        #pragma unroll
        for (int g = 1; g < 8; g++) {
            float v  = rv[g * TM + tid];
            int   ix = ri[g * TM + tid];
            if (v < bv || (v == bv && ix < bi)) { bv = v; bi = ix; }
        }
        int n = b * LL + l0 + tid;
        dout[IDX_OFF + n] = (float)bi;
        ii[tid] = bi;
        g_flags[bi] = 1;                 // idempotent usage mark
        se[tid] = xns[tid] + bv;         // min squared distance (loss term)
    }
    __syncthreads();

    // Block loss reduction -> per-block partial
    if (tid < 64) se[tid] += se[tid + 64];
    __syncthreads();
    if (tid < 32) {
        float s = se[tid] + se[tid + 32];
        #pragma unroll
        for (int off = 16; off > 0; off >>= 1)
            s += __shfl_down_sync(0xffffffffu, s, off);
        if (tid == 0) g_partial[blockIdx.x] = s;
    }

    // Gather + transpose write: out[b][d][l] = emb[idx][d] (coalesced stores)
    __syncthreads();
    for (int i = tid; i < DD * TM; i += THREADS) {
        int d = i >> 7, t = i & 127;
        dout[((size_t)(b * DD + d)) * LL + l0 + t] = emb[(size_t)ii[t] * DD + d];
    }
}

// ---- finalize: loss scalar + usage count; resets flags for next call ----
__global__ void __launch_bounds__(1024, 1)
vq_final(float* __restrict__ dout) {
    __shared__ float lsum;
    __shared__ int   cnt;
    int tid = threadIdx.x;
    if (tid == 0) { lsum = 0.0f; cnt = 0; }
    __syncthreads();

    float s = (tid < NBLK) ? g_partial[tid] : 0.0f;
    #pragma unroll
    for (int off = 16; off > 0; off >>= 1)
        s += __shfl_down_sync(0xffffffffu, s, off);
    if ((tid & 31) == 0) atomicAdd(&lsum, s);

    int f = (tid < KK) ? g_flags[tid] : 0;
    #pragma unroll
    for (int off = 16; off > 0; off >>= 1)
        f += __shfl_down_sync(0xffffffffu, f, off);
    if ((tid & 31) == 0) atomicAdd(&cnt, f);
    __syncthreads();

    if (tid < KK) g_flags[tid] = 0;      // restore zero state for next call
    if (tid == 0) {
        dout[LOSS_OFF]  = 11.0f * lsum / (float)(NN * DD);   // (1+10) * MSE
        dout[USAGE_OFF] = (float)cnt;
    }
}

extern "C" void kernel_launch(void* const* d_in, const int* in_sizes, int n_in,
                              void* d_out, int out_size) {
    (void)n_in; (void)out_size;
    const float* x;
    const float* emb;
    if (in_sizes[0] == KK * DD) { emb = (const float*)d_in[0]; x = (const float*)d_in[1]; }
    else                        { x   = (const float*)d_in[0]; emb = (const float*)d_in[1]; }
    float* out = (float*)d_out;

    const int smem_bytes = 64 * XP_STRIDE * 8        // xsp
                         + KC * ES_STRIDE * 4        // es
                         + (KC + TM + TM) * 4;       // se + xns + ii
    cudaFuncSetAttribute(vq_main, cudaFuncAttributeMaxDynamicSharedMemorySize,
                         smem_bytes);

    vq_main<<<NBLK, THREADS, smem_bytes>>>(x, emb, out);
    vq_final<<<1, 1024>>>(out);
}

// round 5
// speedup vs baseline: 1.3780x; 1.1521x over previous
#include <cuda_runtime.h>
#include <cstdint>

// Problem constants
#define BB   16
#define DD   64
#define LL   2048
#define KK   1000
#define KPAD 1024
#define NN   (BB * LL)          // 32768 tokens
#define TM   128                // tokens per block
#define KC   128                // codes per chunk
#define NCHUNK (KPAD / KC)      // 8
#define THREADS 256
#define NBLK (NN / TM)          // 256 blocks
#define XS_STRIDE 132           // floats, [d][t] x tile (proven conflict-free)
#define ES_STRIDE 66            // floats: 8*66 = 528 = 16 mod 32 -> erow pair on
                                // DIFFERENT banks (68 gave 544 = 0 mod 32 -> 2-way)

#define OUT_ELEMS (BB * DD * LL)     // 2097152
#define LOSS_OFF  OUT_ELEMS
#define USAGE_OFF (OUT_ELEMS + 1)
#define IDX_OFF   (OUT_ELEMS + 2)

// Per-block loss partials (rewritten every call, no clearing needed).
__device__ float g_partial[NBLK];
// Usage flags: zero at init; vq_main sets, vq_final reads then resets to zero.
__device__ int g_flags[KK];

// ---- packed f32x2 helpers ----
__device__ __forceinline__ unsigned long long ffma2(unsigned long long a,
                                                    unsigned long long b,
                                                    unsigned long long c) {
    unsigned long long d;
    asm("fma.rn.f32x2 %0, %1, %2, %3;" : "=l"(d) : "l"(a), "l"(b), "l"(c));
    return d;
}
__device__ __forceinline__ unsigned long long dup2(float v) {
    unsigned long long r;
    asm("mov.b64 %0, {%1, %1};" : "=l"(r) : "f"(v));
    return r;
}
__device__ __forceinline__ void unpack2(unsigned long long v, float& lo, float& hi) {
    asm("mov.b64 {%0, %1}, %2;" : "=f"(lo), "=f"(hi) : "l"(v));
}

// ---- main: distances + argmin + gather + loss partial + usage marks ----
__global__ void __launch_bounds__(THREADS, 2)
vq_main(const float* __restrict__ x, const float* __restrict__ emb,
        float* __restrict__ dout) {
    extern __shared__ float sm[];
    float* xs  = sm;                               // [64][132]
    float* es  = xs + DD * XS_STRIDE;              // [128][66]
    float* se  = es + KC * ES_STRIDE;              // [128] code norms
    float* xns = se + KC;                          // [128] token norms
    float* rv  = xns + TM;                         // [16][128] reduce vals
    int*   ri  = (int*)(rv + 16 * TM);             // [16][128] reduce idx
    int*   ii  = ri + 16 * TM;                     // [128] final idx

    const int tid = threadIdx.x;
    const int b  = blockIdx.x >> 4;
    const int l0 = (blockIdx.x & 15) * TM;
    const int tt = tid & 15;    // token group (8 tokens as 4 adjacent pairs)
    const int tc = tid >> 4;    // code group (codes tc*8 .. tc*8+7)

    // Load x tile [64][128] transposed to [d][t], coalesced float4
    for (int i = tid; i < DD * (TM / 4); i += THREADS) {
        int d = i >> 5, t4 = i & 31;
        float4 v = *(const float4*)(x + ((size_t)(b * DD + d)) * LL + l0 + t4 * 4);
        *(float4*)(xs + d * XS_STRIDE + t4 * 4) = v;
    }
    __syncthreads();

    // Per-token squared norms (conflict-free column reads)
    if (tid < TM) {
        float s = 0.0f;
        #pragma unroll
        for (int d = 0; d < DD; d++) {
            float v = xs[d * XS_STRIDE + tid];
            s += v * v;
        }
        xns[tid] = s;
    }

    float bestv[8];
    int   besti[8];
    #pragma unroll
    for (int i = 0; i < 8; i++) { bestv[i] = 3.0e38f; besti[i] = 0; }

    for (int c = 0; c < NCHUNK; c++) {
        const int k0 = c * KC;
        __syncthreads();
        // Load code chunk [KC][64] (coalesced float4 reads, float2 stores:
        // row base k*66 keeps 8B alignment, not 16B)
        for (int i = tid; i < KC * (DD / 4); i += THREADS) {
            int k = i >> 4, d4 = i & 15;
            float4 v = make_float4(0.f, 0.f, 0.f, 0.f);
            if (k0 + k < KK)
                v = *(const float4*)(emb + (size_t)(k0 + k) * DD + d4 * 4);
            float* dst = es + k * ES_STRIDE + d4 * 4;
            *(float2*)(dst)     = make_float2(v.x, v.y);
            *(float2*)(dst + 2) = make_float2(v.z, v.w);
        }
        __syncthreads();
        // In-block code norms
        if (tid < KC) {
            if (k0 + tid < KK) {
                const float* row = es + tid * ES_STRIDE;
                float s = 0.0f;
                #pragma unroll
                for (int d2 = 0; d2 < DD / 2; d2++) {
                    float2 v = *(const float2*)(row + d2 * 2);
                    s += v.x * v.x + v.y * v.y;
                }
                se[tid] = s;
            } else {
                se[tid] = 3.4e38f;  // padded codes never win
            }
        }
        __syncthreads();

        // 8 tokens x 8 codes register tile, token pairs packed in f32x2.
        // Pair p holds tokens (2*tt + 32*p, 2*tt + 32*p + 1) -> u64 bank 2*tt:
        // conflict-free. erow: 2 addrs/warp, Delta = 528 words = 16 mod 32:
        // different banks -> 1 wavefront broadcast.
        unsigned long long acc[8][4];
        #pragma unroll
        for (int j = 0; j < 8; j++)
            #pragma unroll
            for (int p = 0; p < 4; p++) acc[j][p] = 0ull;

        const float* erow = es + (tc * 8) * ES_STRIDE;
        #pragma unroll 2
        for (int d = 0; d < DD; d++) {
            const unsigned long long* xrow =
                (const unsigned long long*)(xs + d * XS_STRIDE);
            unsigned long long xp0 = xrow[tt];
            unsigned long long xp1 = xrow[tt + 16];
            unsigned long long xp2 = xrow[tt + 32];
            unsigned long long xp3 = xrow[tt + 48];
            #pragma unroll
            for (int j = 0; j < 8; j++) {
                unsigned long long e2 = dup2(erow[j * ES_STRIDE + d]);
                acc[j][0] = ffma2(xp0, e2, acc[j][0]);
                acc[j][1] = ffma2(xp1, e2, acc[j][1]);
                acc[j][2] = ffma2(xp2, e2, acc[j][2]);
                acc[j][3] = ffma2(xp3, e2, acc[j][3]);
            }
        }

        // argmin update: m = ||e||^2 - 2*dot   (||x||^2 added at the end)
        #pragma unroll
        for (int j = 0; j < 8; j++) {
            int   kk = k0 + tc * 8 + j;
            float en = se[tc * 8 + j];
            #pragma unroll
            for (int p = 0; p < 4; p++) {
                float d0, d1;
                unpack2(acc[j][p], d0, d1);
                float m0 = fmaf(-2.0f, d0, en);
                float m1 = fmaf(-2.0f, d1, en);
                if (m0 < bestv[2 * p])     { bestv[2 * p]     = m0; besti[2 * p]     = kk; }
                if (m1 < bestv[2 * p + 1]) { bestv[2 * p + 1] = m1; besti[2 * p + 1] = kk; }
            }
        }
    }

    // Cross-thread (over tc) argmin reduction
    __syncthreads();
    #pragma unroll
    for (int p = 0; p < 4; p++) {
        int t = 2 * tt + 32 * p;
        rv[tc * TM + t]     = bestv[2 * p];
        ri[tc * TM + t]     = besti[2 * p];
        rv[tc * TM + t + 1] = bestv[2 * p + 1];
        ri[tc * TM + t + 1] = besti[2 * p + 1];
    }
    __syncthreads();

    if (tid < TM) {
        float bv = rv[tid];
        int   bi = ri[tid];
        #pragma unroll
        for (int g = 1; g < 16; g++) {
            float v  = rv[g * TM + tid];
            int   ix = ri[g * TM + tid];
            if (v < bv || (v == bv && ix < bi)) { bv = v; bi = ix; }
        }
        int n = b * LL + l0 + tid;
        dout[IDX_OFF + n] = (float)bi;
        ii[tid] = bi;
        g_flags[bi] = 1;                 // idempotent usage mark
        rv[tid] = xns[tid] + bv;         // min squared distance (loss term)
    }
    __syncthreads();

    // Block loss reduction -> per-block partial
    if (tid < 64) rv[tid] += rv[tid + 64];
    __syncthreads();
    if (tid < 32) {
        float s = rv[tid] + rv[tid + 32];
        #pragma unroll
        for (int off = 16; off > 0; off >>= 1)
            s += __shfl_down_sync(0xffffffffu, s, off);
        if (tid == 0) g_partial[blockIdx.x] = s;
    }

    // Gather + transpose write: out[b][d][l] = emb[idx][d] (coalesced stores)
    __syncthreads();
    for (int i = tid; i < DD * TM; i += THREADS) {
        int d = i >> 7, t = i & 127;
        dout[((size_t)(b * DD + d)) * LL + l0 + t] = emb[(size_t)ii[t] * DD + d];
    }
}

// ---- finalize: loss scalar + usage count; resets flags for next call ----
__global__ void __launch_bounds__(1024, 1)
vq_final(float* __restrict__ dout) {
    __shared__ float lsum;
    __shared__ int   cnt;
    int tid = threadIdx.x;
    if (tid == 0) { lsum = 0.0f; cnt = 0; }
    __syncthreads();

    float s = (tid < NBLK) ? g_partial[tid] : 0.0f;
    #pragma unroll
    for (int off = 16; off > 0; off >>= 1)
        s += __shfl_down_sync(0xffffffffu, s, off);
    if ((tid & 31) == 0) atomicAdd(&lsum, s);

    int f = (tid < KK) ? g_flags[tid] : 0;
    #pragma unroll
    for (int off = 16; off > 0; off >>= 1)
        f += __shfl_down_sync(0xffffffffu, f, off);
    if ((tid & 31) == 0) atomicAdd(&cnt, f);
    __syncthreads();

    if (tid < KK) g_flags[tid] = 0;      // restore zero state for next call
    if (tid == 0) {
        dout[LOSS_OFF]  = 11.0f * lsum / (float)(NN * DD);   // (1+10) * MSE
        dout[USAGE_OFF] = (float)cnt;
    }
}

extern "C" void kernel_launch(void* const* d_in, const int* in_sizes, int n_in,
                              void* d_out, int out_size) {
    (void)n_in; (void)out_size;
    const float* x;
    const float* emb;
    if (in_sizes[0] == KK * DD) { emb = (const float*)d_in[0]; x = (const float*)d_in[1]; }
    else                        { x   = (const float*)d_in[0]; emb = (const float*)d_in[1]; }
    float* out = (float*)d_out;

    const int smem_bytes =
        (DD * XS_STRIDE + KC * ES_STRIDE + KC + TM + 16 * TM) * 4  // floats
        + (16 * TM + TM) * 4;                                      // ints
    cudaFuncSetAttribute(vq_main, cudaFuncAttributeMaxDynamicSharedMemorySize,
                         smem_bytes);

    vq_main<<<NBLK, THREADS, smem_bytes>>>(x, emb, out);
    vq_final<<<1, 1024>>>(out);
}

// round 6
// speedup vs baseline: 1.3806x; 1.0019x over previous
#include <cuda_runtime.h>
#include <cstdint>

// Problem constants
#define BB   16
#define DD   64
#define LL   2048
#define KK   1000
#define KPAD 1024
#define NN   (BB * LL)          // 32768 tokens
#define TM   128                // tokens per block
#define KC   128                // codes per chunk
#define NCHUNK (KPAD / KC)      // 8
#define THREADS 256
#define NBLK (NN / TM)          // 256 blocks
#define XS_STRIDE 132           // floats, [d][t] x tile (proven conflict-free)
#define ES_STRIDE 66            // floats: 8*66 = 528 = 16 mod 32 -> erow pair on
                                // DIFFERENT banks (68 gave 544 = 0 mod 32 -> 2-way)

#define OUT_ELEMS (BB * DD * LL)     // 2097152
#define LOSS_OFF  OUT_ELEMS
#define USAGE_OFF (OUT_ELEMS + 1)
#define IDX_OFF   (OUT_ELEMS + 2)

// Per-block loss partials (rewritten every call, no clearing needed).
__device__ float g_partial[NBLK];
// Usage flags: zero at init; vq_main sets, vq_final reads then resets to zero.
__device__ int g_flags[KK];

// ---- packed f32x2 helpers ----
__device__ __forceinline__ unsigned long long ffma2(unsigned long long a,
                                                    unsigned long long b,
                                                    unsigned long long c) {
    unsigned long long d;
    asm("fma.rn.f32x2 %0, %1, %2, %3;" : "=l"(d) : "l"(a), "l"(b), "l"(c));
    return d;
}
__device__ __forceinline__ unsigned long long dup2(float v) {
    unsigned long long r;
    asm("mov.b64 %0, {%1, %1};" : "=l"(r) : "f"(v));
    return r;
}
__device__ __forceinline__ void unpack2(unsigned long long v, float& lo, float& hi) {
    asm("mov.b64 {%0, %1}, %2;" : "=f"(lo), "=f"(hi) : "l"(v));
}

// ---- main: distances + argmin + gather + loss partial + usage marks ----
__global__ void __launch_bounds__(THREADS, 2)
vq_main(const float* __restrict__ x, const float* __restrict__ emb,
        float* __restrict__ dout) {
    extern __shared__ float sm[];
    float* xs  = sm;                               // [64][132]
    float* es  = xs + DD * XS_STRIDE;              // [128][66]
    float* se  = es + KC * ES_STRIDE;              // [128] code norms
    float* xns = se + KC;                          // [128] token norms
    float* rv  = xns + TM;                         // [16][128] reduce vals
    int*   ri  = (int*)(rv + 16 * TM);             // [16][128] reduce idx
    int*   ii  = ri + 16 * TM;                     // [128] final idx

    const int tid = threadIdx.x;
    const int b  = blockIdx.x >> 4;
    const int l0 = (blockIdx.x & 15) * TM;
    const int tt = tid & 15;    // token group (8 tokens as 4 adjacent pairs)
    const int tc = tid >> 4;    // code group (codes tc*8 .. tc*8+7)

    // Load x tile [64][128] transposed to [d][t], coalesced float4
    for (int i = tid; i < DD * (TM / 4); i += THREADS) {
        int d = i >> 5, t4 = i & 31;
        float4 v = *(const float4*)(x + ((size_t)(b * DD + d)) * LL + l0 + t4 * 4);
        *(float4*)(xs + d * XS_STRIDE + t4 * 4) = v;
    }
    __syncthreads();

    // Per-token squared norms (conflict-free column reads)
    if (tid < TM) {
        float s = 0.0f;
        #pragma unroll
        for (int d = 0; d < DD; d++) {
            float v = xs[d * XS_STRIDE + tid];
            s += v * v;
        }
        xns[tid] = s;
    }

    float bestv[8];
    int   besti[8];
    #pragma unroll
    for (int i = 0; i < 8; i++) { bestv[i] = 3.0e38f; besti[i] = 0; }

    for (int c = 0; c < NCHUNK; c++) {
        const int k0 = c * KC;
        __syncthreads();
        // Load code chunk [KC][64] (coalesced float4 reads, float2 stores:
        // row base k*66 keeps 8B alignment, not 16B)
        for (int i = tid; i < KC * (DD / 4); i += THREADS) {
            int k = i >> 4, d4 = i & 15;
            float4 v = make_float4(0.f, 0.f, 0.f, 0.f);
            if (k0 + k < KK)
                v = *(const float4*)(emb + (size_t)(k0 + k) * DD + d4 * 4);
            float* dst = es + k * ES_STRIDE + d4 * 4;
            *(float2*)(dst)     = make_float2(v.x, v.y);
            *(float2*)(dst + 2) = make_float2(v.z, v.w);
        }
        __syncthreads();
        // In-block code norms
        if (tid < KC) {
            if (k0 + tid < KK) {
                const float* row = es + tid * ES_STRIDE;
                float s = 0.0f;
                #pragma unroll
                for (int d2 = 0; d2 < DD / 2; d2++) {
                    float2 v = *(const float2*)(row + d2 * 2);
                    s += v.x * v.x + v.y * v.y;
                }
                se[tid] = s;
            } else {
                se[tid] = 3.4e38f;  // padded codes never win
            }
        }
        __syncthreads();

        // 8 tokens x 8 codes register tile, token pairs packed in f32x2.
        // Pair p holds tokens (2*tt + 32*p, 2*tt + 32*p + 1) -> u64 bank 2*tt:
        // conflict-free. erow: 2 addrs/warp, Delta = 528 words = 16 mod 32:
        // different banks -> 1 wavefront broadcast.
        unsigned long long acc[8][4];
        #pragma unroll
        for (int j = 0; j < 8; j++)
            #pragma unroll
            for (int p = 0; p < 4; p++) acc[j][p] = 0ull;

        const float* erow = es + (tc * 8) * ES_STRIDE;
        #pragma unroll 2
        for (int d = 0; d < DD; d++) {
            const unsigned long long* xrow =
                (const unsigned long long*)(xs + d * XS_STRIDE);
            unsigned long long xp0 = xrow[tt];
            unsigned long long xp1 = xrow[tt + 16];
            unsigned long long xp2 = xrow[tt + 32];
            unsigned long long xp3 = xrow[tt + 48];
            #pragma unroll
            for (int j = 0; j < 8; j++) {
                unsigned long long e2 = dup2(erow[j * ES_STRIDE + d]);
                acc[j][0] = ffma2(xp0, e2, acc[j][0]);
                acc[j][1] = ffma2(xp1, e2, acc[j][1]);
                acc[j][2] = ffma2(xp2, e2, acc[j][2]);
                acc[j][3] = ffma2(xp3, e2, acc[j][3]);
            }
        }

        // argmin update: m = ||e||^2 - 2*dot   (||x||^2 added at the end)
        #pragma unroll
        for (int j = 0; j < 8; j++) {
            int   kk = k0 + tc * 8 + j;
            float en = se[tc * 8 + j];
            #pragma unroll
            for (int p = 0; p < 4; p++) {
                float d0, d1;
                unpack2(acc[j][p], d0, d1);
                float m0 = fmaf(-2.0f, d0, en);
                float m1 = fmaf(-2.0f, d1, en);
                if (m0 < bestv[2 * p])     { bestv[2 * p]     = m0; besti[2 * p]     = kk; }
                if (m1 < bestv[2 * p + 1]) { bestv[2 * p + 1] = m1; besti[2 * p + 1] = kk; }
            }
        }
    }

    // Cross-thread (over tc) argmin reduction
    __syncthreads();
    #pragma unroll
    for (int p = 0; p < 4; p++) {
        int t = 2 * tt + 32 * p;
        rv[tc * TM + t]     = bestv[2 * p];
        ri[tc * TM + t]     = besti[2 * p];
        rv[tc * TM + t + 1] = bestv[2 * p + 1];
        ri[tc * TM + t + 1] = besti[2 * p + 1];
    }
    __syncthreads();

    if (tid < TM) {
        float bv = rv[tid];
        int   bi = ri[tid];
        #pragma unroll
        for (int g = 1; g < 16; g++) {
            float v  = rv[g * TM + tid];
            int   ix = ri[g * TM + tid];
            if (v < bv || (v == bv && ix < bi)) { bv = v; bi = ix; }
        }
        int n = b * LL + l0 + tid;
        dout[IDX_OFF + n] = (float)bi;
        ii[tid] = bi;
        g_flags[bi] = 1;                 // idempotent usage mark
        rv[tid] = xns[tid] + bv;         // min squared distance (loss term)
    }
    __syncthreads();

    // Block loss reduction -> per-block partial
    if (tid < 64) rv[tid] += rv[tid + 64];
    __syncthreads();
    if (tid < 32) {
        float s = rv[tid] + rv[tid + 32];
        #pragma unroll
        for (int off = 16; off > 0; off >>= 1)
            s += __shfl_down_sync(0xffffffffu, s, off);
        if (tid == 0) g_partial[blockIdx.x] = s;
    }

    // Gather + transpose write: out[b][d][l] = emb[idx][d] (coalesced stores)
    __syncthreads();
    for (int i = tid; i < DD * TM; i += THREADS) {
        int d = i >> 7, t = i & 127;
        dout[((size_t)(b * DD + d)) * LL + l0 + t] = emb[(size_t)ii[t] * DD + d];
    }
}

// ---- finalize: loss scalar + usage count; resets flags for next call ----
__global__ void __launch_bounds__(1024, 1)
vq_final(float* __restrict__ dout) {
    __shared__ float lsum;
    __shared__ int   cnt;
    int tid = threadIdx.x;
    if (tid == 0) { lsum = 0.0f; cnt = 0; }
    __syncthreads();

    float s = (tid < NBLK) ? g_partial[tid] : 0.0f;
    #pragma unroll
    for (int off = 16; off > 0; off >>= 1)
        s += __shfl_down_sync(0xffffffffu, s, off);
    if ((tid & 31) == 0) atomicAdd(&lsum, s);

    int f = (tid < KK) ? g_flags[tid] : 0;
    #pragma unroll
    for (int off = 16; off > 0; off >>= 1)
        f += __shfl_down_sync(0xffffffffu, f, off);
    if ((tid & 31) == 0) atomicAdd(&cnt, f);
    __syncthreads();

    if (tid < KK) g_flags[tid] = 0;      // restore zero state for next call
    if (tid == 0) {
        dout[LOSS_OFF]  = 11.0f * lsum / (float)(NN * DD);   // (1+10) * MSE
        dout[USAGE_OFF] = (float)cnt;
    }
}

extern "C" void kernel_launch(void* const* d_in, const int* in_sizes, int n_in,
                              void* d_out, int out_size) {
    (void)n_in; (void)out_size;
    const float* x;
    const float* emb;
    if (in_sizes[0] == KK * DD) { emb = (const float*)d_in[0]; x = (const float*)d_in[1]; }
    else                        { x   = (const float*)d_in[0]; emb = (const float*)d_in[1]; }
    float* out = (float*)d_out;

    const int smem_bytes =
        (DD * XS_STRIDE + KC * ES_STRIDE + KC + TM + 16 * TM) * 4  // floats
        + (16 * TM + TM) * 4;                                      // ints
    cudaFuncSetAttribute(vq_main, cudaFuncAttributeMaxDynamicSharedMemorySize,
                         smem_bytes);

    vq_main<<<NBLK, THREADS, smem_bytes>>>(x, emb, out);
    vq_final<<<1, 1024>>>(out);
}

// round 8
// speedup vs baseline: 1.8123x; 1.3127x over previous
#include <cuda_runtime.h>
#include <cuda_bf16.h>
#include <cstdint>

#define BB   16
#define DD   64
#define LL   2048
#define KK   1000
#define KPAD 1024
#define NN   (BB * LL)             // 32768 tokens
#define TM2  256                   // tokens per CTA
#define KC   128                   // codes per chunk
#define NCHUNK 8
#define NBLK (NN / TM2)            // 128 CTAs
#define THREADS 256

#define OUT_ELEMS (BB * DD * LL)
#define LOSS_OFF  OUT_ELEMS
#define USAGE_OFF (OUT_ELEMS + 1)
#define IDX_OFF   (OUT_ELEMS + 2)

// SMEM layout (bytes). Token/code row stride = 72 bf16 = 144 B
// (144 = 4 words mod 32 -> all fragment LDS.32 patterns conflict-free).
#define ROWB     144
#define A_BLK    (TM2 * ROWB)          // 36864 per split block
#define SM_A     0                     // 3 blocks: 110592
#define B_BLK    (KC * ROWB)           // 18432 per split block
#define B_BUF    (3 * B_BLK)           // 55296 per buffer
#define SM_B     110592                // 2 buffers: 110592
#define SM_SE    221184                // float[1024] code norms
#define SM_XN    225280                // float[256] token norms
#define SM_RV    226304                // float[256][2]
#define SM_RI    228352                // int[256][2]
#define SM_II    230400                // int[256]
#define SM_LS    231424                // float[8]
#define SM_TOTAL 231488

#define CHUNK_BYTES (3 * KC * DD * 2)  // 49152 per chunk image

__device__ __align__(16) unsigned short g_esplit[NCHUNK][3 * KC * DD];
__device__ float g_enorm[KPAD];
__device__ float g_partial[NBLK];
__device__ int   g_flags[KK];

// ---------------- helpers ----------------
__device__ __forceinline__ uint32_t smem_u32(const void* p) {
    uint32_t a;
    asm("{ .reg .u64 t; cvta.to.shared.u64 t, %1; cvt.u32.u64 %0, t; }"
        : "=r"(a) : "l"(p));
    return a;
}
__device__ __forceinline__ uint32_t lds32(uint32_t a) {
    uint32_t v;
    asm("ld.shared.b32 %0, [%1];" : "=r"(v) : "r"(a));
    return v;
}
__device__ __forceinline__ void sts32(uint32_t a, uint32_t v) {
    asm volatile("st.shared.b32 [%0], %1;" :: "r"(a), "r"(v) : "memory");
}
__device__ __forceinline__ void mma16816(float* c, const uint32_t* a,
                                         uint32_t b0, uint32_t b1) {
    asm volatile("mma.sync.aligned.m16n8k16.row.col.f32.bf16.bf16.f32 "
                 "{%0,%1,%2,%3}, {%4,%5,%6,%7}, {%8,%9}, {%0,%1,%2,%3};"
                 : "+f"(c[0]), "+f"(c[1]), "+f"(c[2]), "+f"(c[3])
                 : "r"(a[0]), "r"(a[1]), "r"(a[2]), "r"(a[3]),
                   "r"(b0), "r"(b1));
}
#define CP_ASYNC16(dst, src) \
    asm volatile("cp.async.cg.shared.global [%0], [%1], 16;" \
                 :: "r"(dst), "l"(src) : "memory")
#define CP_COMMIT() asm volatile("cp.async.commit_group;" ::: "memory")
#define CP_WAIT0()  asm volatile("cp.async.wait_group 0;" ::: "memory")

// ---- prep: 3-way bf16 split of codebook + fp32 norms ----
__global__ void __launch_bounds__(256, 4)
vq_prep(const float* __restrict__ emb) {
    __shared__ float hsum[8];
    int tid = threadIdx.x;
    int idx = blockIdx.x * 256 + tid;
    int k = idx >> 6, d = idx & 63;
    float e = (k < KK) ? emb[(size_t)k * DD + d] : 0.0f;

    float pn = e * e;
    #pragma unroll
    for (int off = 16; off > 0; off >>= 1)
        pn += __shfl_xor_sync(0xffffffffu, pn, off);
    if ((tid & 31) == 0) hsum[tid >> 5] = pn;

    __nv_bfloat16 b1 = __float2bfloat16(e);
    float r1 = e - __bfloat162float(b1);
    __nv_bfloat16 b2 = __float2bfloat16(r1);
    __nv_bfloat16 b3 = __float2bfloat16(r1 - __bfloat162float(b2));

    int ch = k >> 7, kc = k & 127;
    unsigned short* base = &g_esplit[ch][0];
    base[(0 * KC + kc) * DD + d] = __bfloat16_as_ushort(b1);
    base[(1 * KC + kc) * DD + d] = __bfloat16_as_ushort(b2);
    base[(2 * KC + kc) * DD + d] = __bfloat16_as_ushort(b3);

    __syncthreads();
    if (tid < 4) {
        int kk2 = blockIdx.x * 4 + tid;
        g_enorm[kk2] = (kk2 < KK) ? (hsum[2 * tid] + hsum[2 * tid + 1]) : 3.4e38f;
    }
}

// ---- main: HMMA split-GEMM distances + argmin + gather + loss ----
__global__ void __launch_bounds__(THREADS, 1)
vq_main(const float* __restrict__ x, const float* __restrict__ emb,
        float* __restrict__ dout) {
    extern __shared__ char smem[];
    const uint32_t sb = smem_u32(smem);
    float* se  = (float*)(smem + SM_SE);
    float* xns = (float*)(smem + SM_XN);
    float* rv2 = (float*)(smem + SM_RV);
    int*   ri2 = (int*)(smem + SM_RI);
    int*   ii  = (int*)(smem + SM_II);
    float* ls  = (float*)(smem + SM_LS);

    const int tid  = threadIdx.x;
    const int warp = tid >> 5;
    const int lane = tid & 31;
    const int wm   = warp & 3;     // m-slice (64 tokens)
    const int wn   = warp >> 2;    // n-slice (64 codes)
    const int lq   = lane >> 2;    // 0..7
    const int lr   = lane & 3;     // 0..3
    const int b    = blockIdx.x >> 3;
    const int l0   = (blockIdx.x & 7) * TM2;

    // Start B chunk-0 copy early (cp.async, overlaps A build)
    {
        const char* src = (const char*)&g_esplit[0][0];
        uint32_t dstb = sb + SM_B;
        for (int i = tid; i < CHUNK_BYTES / 16; i += THREADS) {
            int row = i >> 3, q = i & 7;
            CP_ASYNC16(dstb + row * ROWB + q * 16, src + row * 128 + q * 16);
        }
        CP_COMMIT();
    }

    // A build: thread owns token t = tid; coalesced global reads per d.
    {
        const float* xp = x + (size_t)b * DD * LL + l0 + tid;
        float xn = 0.0f;
        #pragma unroll 4
        for (int d = 0; d < DD; d += 2) {
            float v0 = xp[(size_t)d * LL];
            float v1 = xp[(size_t)(d + 1) * LL];
            xn += v0 * v0 + v1 * v1;
            __nv_bfloat16 a1 = __float2bfloat16(v0);
            float r = v0 - __bfloat162float(a1);
            __nv_bfloat16 a2 = __float2bfloat16(r);
            __nv_bfloat16 a3 = __float2bfloat16(r - __bfloat162float(a2));
            __nv_bfloat16 c1 = __float2bfloat16(v1);
            float q = v1 - __bfloat162float(c1);
            __nv_bfloat16 c2 = __float2bfloat16(q);
            __nv_bfloat16 c3 = __float2bfloat16(q - __bfloat162float(c2));
            uint32_t base = sb + SM_A + tid * ROWB + d * 2;
            sts32(base,             (uint32_t)__bfloat16_as_ushort(a1) |
                                    ((uint32_t)__bfloat16_as_ushort(c1) << 16));
            sts32(base + A_BLK,     (uint32_t)__bfloat16_as_ushort(a2) |
                                    ((uint32_t)__bfloat16_as_ushort(c2) << 16));
            sts32(base + 2 * A_BLK, (uint32_t)__bfloat16_as_ushort(a3) |
                                    ((uint32_t)__bfloat16_as_ushort(c3) << 16));
        }
        xns[tid] = xn;
    }
    // Code norms to smem
    for (int i = tid; i < KPAD; i += THREADS) se[i] = g_enorm[i];

    CP_WAIT0();
    __syncthreads();

    float bestv[8];
    int   besti[8];
    #pragma unroll
    for (int s = 0; s < 8; s++) { bestv[s] = 3.0e38f; besti[s] = 0; }

    const uint32_t aW = sb + SM_A + wm * 64 * ROWB + lq * ROWB + lr * 4;
    const uint32_t bW = sb + SM_B + wn * 64 * ROWB + lq * ROWB + lr * 4;

    for (int c = 0; c < NCHUNK; c++) {
        const int buf = c & 1;
        // issue next chunk copy into the other buffer
        if (c + 1 < NCHUNK) {
            const char* src = (const char*)&g_esplit[c + 1][0];
            uint32_t dstb = sb + SM_B + ((c + 1) & 1) * B_BUF;
            for (int i = tid; i < CHUNK_BYTES / 16; i += THREADS) {
                int row = i >> 3, q = i & 7;
                CP_ASYNC16(dstb + row * ROWB + q * 16, src + row * 128 + q * 16);
            }
            CP_COMMIT();
        }

        float acc[4][8][4];
        #pragma unroll
        for (int mt = 0; mt < 4; mt++)
            #pragma unroll
            for (int nt = 0; nt < 8; nt++)
                #pragma unroll
                for (int r = 0; r < 4; r++) acc[mt][nt][r] = 0.0f;

        // 6 split-product pairs x 4 k-steps of 16
        for (int p = 0; p < 6; p++) {
            int pa = (p < 3) ? p : ((p < 5) ? p - 3 : 0);
            int pb = (p < 3) ? 0 : ((p < 5) ? 1 : 2);
            uint32_t ab = aW + pa * A_BLK;
            uint32_t bb = bW + buf * B_BUF + pb * B_BLK;
            #pragma unroll
            for (int ks = 0; ks < 4; ks++) {
                uint32_t ko = ks * 32;           // 16 bf16 = 32 bytes
                uint32_t a[4][4];
                #pragma unroll
                for (int mt = 0; mt < 4; mt++) {
                    uint32_t base = ab + mt * 16 * ROWB + ko;
                    a[mt][0] = lds32(base);
                    a[mt][1] = lds32(base + 8 * ROWB);
                    a[mt][2] = lds32(base + 16);
                    a[mt][3] = lds32(base + 8 * ROWB + 16);
                }
                #pragma unroll
                for (int nt = 0; nt < 8; nt++) {
                    uint32_t bbase = bb + nt * 8 * ROWB + ko;
                    uint32_t b0 = lds32(bbase);
                    uint32_t b1 = lds32(bbase + 16);
                    #pragma unroll
                    for (int mt = 0; mt < 4; mt++)
                        mma16816(acc[mt][nt], a[mt], b0, b1);
                }
            }
        }

        // Argmin on this chunk's distances (acc = dot products)
        #pragma unroll
        for (int nt = 0; nt < 8; nt++) {
            int cbase = c * KC + wn * 64 + nt * 8 + lr * 2;
            float2 en = *(const float2*)(se + cbase);
            #pragma unroll
            for (int mt = 0; mt < 4; mt++) {
                #pragma unroll
                for (int h = 0; h < 2; h++) {
                    int s = mt * 2 + h;
                    float m0 = fmaf(-2.0f, acc[mt][nt][2 * h],     en.x);
                    float m1 = fmaf(-2.0f, acc[mt][nt][2 * h + 1], en.y);
                    if (m0 < bestv[s] || (m0 == bestv[s] && cbase < besti[s]))
                        { bestv[s] = m0; besti[s] = cbase; }
                    if (m1 < bestv[s] || (m1 == bestv[s] && cbase + 1 < besti[s]))
                        { bestv[s] = m1; besti[s] = cbase + 1; }
                }
            }
        }

        CP_WAIT0();
        __syncthreads();
    }

    // Reduce across the 4 lanes (lr) sharing each token row
    #pragma unroll
    for (int s = 0; s < 8; s++) {
        #pragma unroll
        for (int off = 1; off <= 2; off <<= 1) {
            float ov = __shfl_xor_sync(0xffffffffu, bestv[s], off);
            int   oi = __shfl_xor_sync(0xffffffffu, besti[s], off);
            if (ov < bestv[s] || (ov == bestv[s] && oi < besti[s]))
                { bestv[s] = ov; besti[s] = oi; }
        }
    }
    if (lr == 0) {
        #pragma unroll
        for (int mt = 0; mt < 4; mt++)
            #pragma unroll
            for (int h = 0; h < 2; h++) {
                int t = wm * 64 + mt * 16 + lq + 8 * h;
                rv2[t * 2 + wn] = bestv[mt * 2 + h];
                ri2[t * 2 + wn] = besti[mt * 2 + h];
            }
    }
    __syncthreads();

    // Final per-token merge of the 2 n-groups + outputs
    {
        float bv = rv2[tid * 2];
        int   bi = ri2[tid * 2];
        float v  = rv2[tid * 2 + 1];
        int   ix = ri2[tid * 2 + 1];
        if (v < bv || (v == bv && ix < bi)) { bv = v; bi = ix; }
        dout[IDX_OFF + b * LL + l0 + tid] = (float)bi;
        ii[tid] = bi;
        g_flags[bi] = 1;
        float sd = xns[tid] + bv;
        #pragma unroll
        for (int off = 16; off > 0; off >>= 1)
            sd += __shfl_down_sync(0xffffffffu, sd, off);
        if (lane == 0) ls[warp] = sd;
    }
    __syncthreads();
    if (tid == 0) {
        float s = 0.0f;
        #pragma unroll
        for (int w = 0; w < 8; w++) s += ls[w];
        g_partial[blockIdx.x] = s;
    }

    // Gather + transpose write (coalesced stores)
    for (int i = tid; i < DD * TM2; i += THREADS) {
        int d = i >> 8, t = i & 255;
        dout[((size_t)(b * DD + d)) * LL + l0 + t] = emb[(size_t)ii[t] * DD + d];
    }
}

// ---- finalize: loss scalar + usage count; resets flags ----
__global__ void __launch_bounds__(1024, 1)
vq_final(float* __restrict__ dout) {
    __shared__ float lsum;
    __shared__ int   cnt;
    int tid = threadIdx.x;
    if (tid == 0) { lsum = 0.0f; cnt = 0; }
    __syncthreads();

    float s = (tid < NBLK) ? g_partial[tid] : 0.0f;
    #pragma unroll
    for (int off = 16; off > 0; off >>= 1)
        s += __shfl_down_sync(0xffffffffu, s, off);
    if ((tid & 31) == 0) atomicAdd(&lsum, s);

    int f = (tid < KK) ? g_flags[tid] : 0;
    #pragma unroll
    for (int off = 16; off > 0; off >>= 1)
        f += __shfl_down_sync(0xffffffffu, f, off);
    if ((tid & 31) == 0) atomicAdd(&cnt, f);
    __syncthreads();

    if (tid < KK) g_flags[tid] = 0;
    if (tid == 0) {
        dout[LOSS_OFF]  = 11.0f * lsum / (float)(NN * DD);
        dout[USAGE_OFF] = (float)cnt;
    }
}

extern "C" void kernel_launch(void* const* d_in, const int* in_sizes, int n_in,
                              void* d_out, int out_size) {
    (void)n_in; (void)out_size;
    const float* x;
    const float* emb;
    if (in_sizes[0] == KK * DD) { emb = (const float*)d_in[0]; x = (const float*)d_in[1]; }
    else                        { x   = (const float*)d_in[0]; emb = (const float*)d_in[1]; }
    float* out = (float*)d_out;

    cudaFuncSetAttribute(vq_main, cudaFuncAttributeMaxDynamicSharedMemorySize,
                         SM_TOTAL);

    vq_prep<<<KPAD / 4, 256>>>(emb);
    vq_main<<<NBLK, THREADS, SM_TOTAL>>>(x, emb, out);
    vq_final<<<1, 1024>>>(out);
}